// round 11
// baseline (speedup 1.0000x reference)
#include <cuda_runtime.h>
#include <cstdint>

#define S_DIM 51
#define B_DIM 2048
#define H_DIM 1024
#define OUT_DIM 904
#define NC 320                  /* compact cols: 4 cmd + 300 logmix + 16 pad */
#define M_DIM (S_DIM * B_DIM)   /* 104448 */
#define NARG (M_DIM * 6)
#define NEG_BIG (-1.0e30f)
#define MARGIN 2.5e-3f

__device__ float g_fc2[(size_t)M_DIM * NC];     /* 133.7 MB */
__device__ float gWc[NC * H_DIM];
__device__ float g_bc[NC];
__device__ int g_karr[NARG];
__device__ int g_ccnt, g_mcnt;
__device__ int g_clist[M_DIM];
__device__ int g_mlist[NARG];

// ---------------- Threefry / sampling helpers (proven exact R4/R8) ----------------
__device__ __forceinline__ uint2 tf2x32(uint32_t k0, uint32_t k1, uint32_t c0, uint32_t c1) {
    uint32_t ks2 = k0 ^ k1 ^ 0x1BD11BDAu;
    uint32_t x0 = c0 + k0, x1 = c1 + k1;
    uint32_t ks[3] = {k0, k1, ks2};
    const int RA[4] = {13, 15, 26, 6};
    const int RB[4] = {17, 29, 16, 24};
#pragma unroll
    for (int blk = 0; blk < 5; blk++) {
        const int* rr = (blk & 1) ? RB : RA;
#pragma unroll
        for (int i = 0; i < 4; i++) { x0 += x1; x1 = __funnelshift_l(x1, x1, rr[i]); x1 ^= x0; }
        x0 += ks[(blk + 1) % 3];
        x1 += ks[(blk + 2) % 3] + (uint32_t)(blk + 1);
    }
    return make_uint2(x0, x1);
}
__device__ __forceinline__ uint32_t rand32(uint32_t k0, uint32_t k1, uint32_t idx) {
    uint2 r = tf2x32(k0, k1, 0u, idx);
    return r.x ^ r.y;
}
__device__ __forceinline__ float gumbel_u32(uint32_t bits) {
    float f = __uint_as_float((bits >> 9) | 0x3f800000u) - 1.0f;
    float u = fmaxf(f, 1.17549435e-38f);
    return -logf(-logf(u));
}
__device__ __forceinline__ float normal_u32(uint32_t bits) {
    float f = __uint_as_float((bits >> 9) | 0x3f800000u) - 1.0f;
    const float lo = -0.99999994f;
    float u = fmaxf(f * 2.0f + lo, lo);
    return 1.41421356237f * erfinvf(u);
}

__global__ void zero_counters() { g_ccnt = 0; g_mcnt = 0; }

// ---------------- compact W: rows {0..3} + {4+j*150+c : j<6, c<50}, pad zeros ----------------
__global__ void build_Wc(const float* __restrict__ W, const float* __restrict__ bias) {
    int i = blockIdx.x * blockDim.x + threadIdx.x;
    if (i >= NC * H_DIM / 4) return;
    const int row = i >> 8;
    int src;
    if (row < 4) src = row;
    else if (row < 304) { const int t = row - 4; src = 4 + (t / 50) * 150 + (t % 50); }
    else src = -1;
    ((float4*)gWc)[i] = (src >= 0)
        ? ((const float4*)W)[(size_t)src * (H_DIM / 4) + (i & 255)]
        : make_float4(0.f, 0.f, 0.f, 0.f);
    if ((i & 255) == 0) g_bc[row] = (src >= 0) ? bias[src] : 0.0f;
}

// ---------------- GEMM: 256x64 CTA tile, 8x8 microtile, BK=8 ----------------
#define BM 256
#define BN 64
#define BK 8

__global__ __launch_bounds__(256)
void gemm_kernel(const float* __restrict__ A) {
    __shared__ float As[BK][BM + 4];
    __shared__ float Bs[BK][BN + 4];

    const int tid = threadIdx.x;
    const int tcol = tid & 7;       // 8 col-groups of 8
    const int trow = tid >> 3;      // 32 row-groups of 8
    const int row0 = blockIdx.y * BM;
    const int col0 = blockIdx.x * BN;

    float acc[8][8];
#pragma unroll
    for (int i = 0; i < 8; i++)
#pragma unroll
        for (int j = 0; j < 8; j++) acc[i][j] = 0.0f;

    // global load mapping (per BK=8 chunk):
    // A: 512 float4 -> 2 per thread: idx = tid, tid+256; row = idx>>1, f = idx&1
    // B: 128 float4 -> tid<128: row = tid>>1, f = tid&1
    const int ar0 = tid >> 1, ar1 = ar0 + 128;
    const int af = (tid & 1) << 2;
    const bool bact = tid < 128;
    const int br = tid >> 1;

    const float* Ap0 = A + (size_t)(row0 + ar0) * H_DIM + af;
    const float* Ap1 = A + (size_t)(row0 + ar1) * H_DIM + af;
    const float* Wp  = gWc + (size_t)(col0 + br) * H_DIM + af;

    float4 pa0 = *(const float4*)Ap0;
    float4 pa1 = *(const float4*)Ap1;
    float4 pb = bact ? *(const float4*)Wp : make_float4(0.f, 0.f, 0.f, 0.f);

    for (int k0 = 0; k0 < H_DIM; k0 += BK) {
        As[af + 0][ar0] = pa0.x; As[af + 1][ar0] = pa0.y;
        As[af + 2][ar0] = pa0.z; As[af + 3][ar0] = pa0.w;
        As[af + 0][ar1] = pa1.x; As[af + 1][ar1] = pa1.y;
        As[af + 2][ar1] = pa1.z; As[af + 3][ar1] = pa1.w;
        if (bact) {
            Bs[af + 0][br] = pb.x; Bs[af + 1][br] = pb.y;
            Bs[af + 2][br] = pb.z; Bs[af + 3][br] = pb.w;
        }
        __syncthreads();

        const int kn = k0 + BK;
        if (kn < H_DIM) {
            pa0 = *(const float4*)(Ap0 + kn);
            pa1 = *(const float4*)(Ap1 + kn);
            if (bact) pb = *(const float4*)(Wp + kn);
        }

#pragma unroll
        for (int k = 0; k < BK; k++) {
            float4 a0 = *(const float4*)(&As[k][trow * 8]);
            float4 a1 = *(const float4*)(&As[k][trow * 8 + 4]);
            float4 b0 = *(const float4*)(&Bs[k][tcol * 8]);
            float4 b1 = *(const float4*)(&Bs[k][tcol * 8 + 4]);
            float av[8] = {a0.x, a0.y, a0.z, a0.w, a1.x, a1.y, a1.z, a1.w};
            float bv[8] = {b0.x, b0.y, b0.z, b0.w, b1.x, b1.y, b1.z, b1.w};
#pragma unroll
            for (int i = 0; i < 8; i++)
#pragma unroll
                for (int j = 0; j < 8; j++)
                    acc[i][j] = fmaf(av[i], bv[j], acc[i][j]);
        }
        __syncthreads();
    }

    const int c = col0 + tcol * 8;
    const float4 bb0 = *(const float4*)(g_bc + c);
    const float4 bb1 = *(const float4*)(g_bc + c + 4);
#pragma unroll
    for (int i = 0; i < 8; i++) {
        const int r = row0 + trow * 8 + i;
        float4 o0, o1;
        o0.x = acc[i][0] + bb0.x; o0.y = acc[i][1] + bb0.y;
        o0.z = acc[i][2] + bb0.z; o0.w = acc[i][3] + bb0.w;
        o1.x = acc[i][4] + bb1.x; o1.y = acc[i][5] + bb1.y;
        o1.z = acc[i][6] + bb1.z; o1.w = acc[i][7] + bb1.w;
        *(float4*)(g_fc2 + (size_t)r * NC + c) = o0;
        *(float4*)(g_fc2 + (size_t)r * NC + c + 4) = o1;
    }
}

// ---------------- command: fast path or push to worklist ----------------
__global__ void command_kernel(float* __restrict__ out) {
    const int row = blockIdx.x * blockDim.x + threadIdx.x;
    if (row >= M_DIM) return;
    const float4 x4 = *(const float4*)(g_fc2 + (size_t)row * NC);
    float x[4] = {x4.x, x4.y, x4.z, x4.w};

    int best = 0; float m = x[0];
#pragma unroll
    for (int c = 1; c < 4; c++) if (x[c] > m) { m = x[c]; best = c; }
    int nnear = 0;
#pragma unroll
    for (int c = 0; c < 4; c++) nnear += (x[c] > m - MARGIN) ? 1 : 0;

    if (nnear > 1) {
        int slot = atomicAdd(&g_ccnt, 1);
        g_clist[slot] = row;
        return;
    }
    float2* o = (float2*)(out + (size_t)row * 10);
    o[0] = make_float2(best == 0 ? 1.f : 0.f, best == 1 ? 1.f : 0.f);
    o[1] = make_float2(best == 2 ? 1.f : 0.f, best == 3 ? 1.f : 0.f);
}

// ---------------- mixture: record winning k (or -1 + worklist) ----------------
__global__ void mixture_kernel() {
    const int gwarp = (blockIdx.x * blockDim.x + threadIdx.x) >> 5;
    const int lane = threadIdx.x & 31;
    if (gwarp >= NARG) return;

    const int sbr = gwarp / 6;
    const int j = gwarp - sbr * 6;
    const float* base = g_fc2 + (size_t)sbr * NC + 4 + j * 50;

    const float x0 = base[lane];
    const float x1 = (lane < 18) ? base[32 + lane] : NEG_BIG;

    float m = fmaxf(x0, x1);
#pragma unroll
    for (int o = 16; o; o >>= 1) m = fmaxf(m, __shfl_xor_sync(0xffffffffu, m, o));

    const float th = m - MARGIN;
    const unsigned f0 = __ballot_sync(0xffffffffu, x0 > th);
    const unsigned f1 = __ballot_sync(0xffffffffu, x1 > th);

    if (lane == 0) {
        if (__popc(f0) + __popc(f1) != 1) {
            g_karr[gwarp] = -1;
            int slot = atomicAdd(&g_mcnt, 1);
            g_mlist[slot] = gwarp;
        } else {
            g_karr[gwarp] = f0 ? (__ffs(f0) - 1) : (31 + __ffs(f1));
        }
    }
}

// ---------------- gather: per row, chosen mean/logstd dots + write args ----------------
__global__ __launch_bounds__(384)
void gather_kernel(const float* __restrict__ A, const float* __restrict__ W,
                   const float* __restrict__ bias, float* __restrict__ out,
                   uint32_t kg0, uint32_t kg1) {
    __shared__ float sa[H_DIM];
    __shared__ float sval[12];
    const int sbr = blockIdx.x;
    const int tid = threadIdx.x;
    const int warp = tid >> 5, lane = tid & 31;

    {
        const float4* src = (const float4*)(A + (size_t)sbr * H_DIM);
        if (tid < 256) ((float4*)sa)[tid] = src[tid];
    }
    __syncthreads();

    const int j = warp >> 1, which = warp & 1;
    const int k = g_karr[sbr * 6 + j];
    if (k >= 0) {
        const int col = 4 + j * 150 + 50 + which * 50 + k;
        const float4* w4 = (const float4*)(W + (size_t)col * H_DIM);
        const float4* s4 = (const float4*)sa;
        float acc = 0.0f;
#pragma unroll
        for (int t = 0; t < 8; t++) {
            const float4 wv = w4[t * 32 + lane];
            const float4 av = s4[t * 32 + lane];
            acc = fmaf(av.x, wv.x, acc);
            acc = fmaf(av.y, wv.y, acc);
            acc = fmaf(av.z, wv.z, acc);
            acc = fmaf(av.w, wv.w, acc);
        }
#pragma unroll
        for (int o = 16; o; o >>= 1) acc += __shfl_xor_sync(0xffffffffu, acc, o);
        if (lane == 0) sval[warp] = acc + bias[col];
    }
    __syncthreads();

    if (tid < 6) {
        const int kk = g_karr[sbr * 6 + tid];
        if (kk >= 0) {
            const float mean = sval[tid * 2];
            const float lstd = sval[tid * 2 + 1];
            const float n = normal_u32(rand32(kg0, kg1, (uint32_t)(sbr * 6 + tid)));
            out[(size_t)sbr * 10 + 4 + tid] = mean + expf(lstd) * (n * 0.01f);
        }
    }
}

// ---------------- cmd fixup: exact sequential recompute (proven R8) ----------------
__global__ void cmd_fixup(const float* __restrict__ A, const float* __restrict__ W,
                          const float* __restrict__ bias, float* __restrict__ out,
                          uint32_t kc0, uint32_t kc1) {
    const int nwarp = (gridDim.x * blockDim.x) >> 5;
    const int lane = threadIdx.x & 31;
    for (int e = (blockIdx.x * blockDim.x + threadIdx.x) >> 5; e < g_ccnt; e += nwarp) {
        const int row = g_clist[e];
        float sc = NEG_BIG;
        if (lane < 4) {
            const float* a = A + (size_t)row * H_DIM;
            const float* w = W + (size_t)lane * H_DIM;
            float acc = 0.0f;
            for (int k = 0; k < H_DIM; k++) acc = fmaf(a[k], w[k], acc);
            const float x = acc + bias[lane];
            sc = gumbel_u32(rand32(kc0, kc1, (uint32_t)(row * 4 + lane))) +
                 __fdiv_rn(x, 1e-4f);
        }
        int bi = lane;
#pragma unroll
        for (int o = 1; o < 4; o <<= 1) {
            float os = __shfl_xor_sync(0xffffffffu, sc, o);
            int oi = __shfl_xor_sync(0xffffffffu, bi, o);
            if (os > sc || (os == sc && oi < bi)) { sc = os; bi = oi; }
        }
        if (lane == 0) {
            float2* o2 = (float2*)(out + (size_t)row * 10);
            o2[0] = make_float2(bi == 0 ? 1.f : 0.f, bi == 1 ? 1.f : 0.f);
            o2[1] = make_float2(bi == 2 ? 1.f : 0.f, bi == 3 ? 1.f : 0.f);
        }
    }
}

// ---------------- mix fixup: exact sequential recompute incl. mean/logstd ----------------
__global__ __launch_bounds__(64)
void mix_fixup(const float* __restrict__ A, const float* __restrict__ W,
               const float* __restrict__ bias, float* __restrict__ out,
               uint32_t km0, uint32_t km1, uint32_t kg0, uint32_t kg1) {
    __shared__ float sa[H_DIM];
    __shared__ float sx[50];
    for (int e = blockIdx.x; e < g_mcnt; e += gridDim.x) {
        const int gw = g_mlist[e];
        const int sbr = gw / 6;
        const int j = gw - sbr * 6;
        __syncthreads();
        {
            const float4* src = (const float4*)(A + (size_t)sbr * H_DIM);
            float4* dst = (float4*)sa;
            for (int i = threadIdx.x; i < H_DIM / 4; i += 64) dst[i] = src[i];
        }
        __syncthreads();
        const int c = threadIdx.x;
        if (c < 50) {
            const int col = 4 + j * 150 + c;
            const float* w = W + (size_t)col * H_DIM;
            float acc = 0.0f;
            for (int k = 0; k < H_DIM; k++) acc = fmaf(sa[k], w[k], acc);
            sx[c] = acc + bias[col];
        }
        __syncthreads();
        if (threadIdx.x == 0) {
            float m = sx[0];
            for (int i = 1; i < 50; i++) m = fmaxf(m, sx[i]);
            float s = 0.0f;
            for (int i = 0; i < 50; i++) s += expf(sx[i] - m);
            const float lse = logf(s) + m;
            float bsc = NEG_BIG; int bk = 0;
            const uint32_t eb = (uint32_t)gw * 50u;
            for (int i = 0; i < 50; i++) {
                const float g = gumbel_u32(rand32(km0, km1, eb + (uint32_t)i));
                const float sc = g + __fdiv_rn(sx[i] - lse, 1e-4f);
                if (sc > bsc) { bsc = sc; bk = i; }
            }
            const int cm = 4 + j * 150 + 50 + bk;
            const int cl = cm + 50;
            const float* wm = W + (size_t)cm * H_DIM;
            const float* wl = W + (size_t)cl * H_DIM;
            float am = 0.0f, al = 0.0f;
            for (int k = 0; k < H_DIM; k++) {
                am = fmaf(sa[k], wm[k], am);
                al = fmaf(sa[k], wl[k], al);
            }
            const float mean = am + bias[cm];
            const float lstd = al + bias[cl];
            const float n = normal_u32(rand32(kg0, kg1, (uint32_t)gw));
            out[(size_t)sbr * 10 + 4 + j] = mean + expf(lstd) * (n * 0.01f);
        }
    }
}

// ---------------- host threefry ----------------
static inline uint32_t h_rotl(uint32_t v, int r) { return (v << r) | (v >> (32 - r)); }
static void h_tf(uint32_t k0, uint32_t k1, uint32_t c0, uint32_t c1,
                 uint32_t* o0, uint32_t* o1) {
    uint32_t ks2 = k0 ^ k1 ^ 0x1BD11BDAu;
    uint32_t x0 = c0 + k0, x1 = c1 + k1;
    uint32_t ks[3] = {k0, k1, ks2};
    const int RA[4] = {13, 15, 26, 6};
    const int RB[4] = {17, 29, 16, 24};
    for (int blk = 0; blk < 5; blk++) {
        const int* rr = (blk & 1) ? RB : RA;
        for (int i = 0; i < 4; i++) { x0 += x1; x1 = h_rotl(x1, rr[i]); x1 ^= x0; }
        x0 += ks[(blk + 1) % 3];
        x1 += ks[(blk + 2) % 3] + (uint32_t)(blk + 1);
    }
    *o0 = x0; *o1 = x1;
}

extern "C" void kernel_launch(void* const* d_in, const int* in_sizes, int n_in,
                              void* d_out, int out_size) {
    const float* A = (const float*)d_in[0];
    const float* W = (const float*)d_in[1];
    const float* b = (const float*)d_in[2];
    float* out = (float*)d_out;

    uint32_t kc0, kc1, km0, km1, kg0, kg1;
    h_tf(0u, 42u, 0u, 0u, &kc0, &kc1);
    h_tf(0u, 42u, 0u, 1u, &km0, &km1);
    h_tf(0u, 42u, 0u, 2u, &kg0, &kg1);

    zero_counters<<<1, 1>>>();
    build_Wc<<<(NC * H_DIM / 4 + 255) / 256, 256>>>(W, b);
    gemm_kernel<<<dim3(NC / BN, M_DIM / BM), 256>>>(A);
    command_kernel<<<(M_DIM + 255) / 256, 256>>>(out);

    const int mwpb = 8;
    mixture_kernel<<<(NARG + mwpb - 1) / mwpb, mwpb * 32>>>();
    gather_kernel<<<M_DIM, 384>>>(A, W, b, out, kg0, kg1);

    cmd_fixup<<<1024, 256>>>(A, W, b, out, kc0, kc1);
    mix_fixup<<<8192, 64>>>(A, W, b, out, km0, km1, kg0, kg1);
}

// round 16
// speedup vs baseline: 1.1029x; 1.1029x over previous
#include <cuda_runtime.h>
#include <cstdint>

#define S_DIM 51
#define B_DIM 2048
#define H_DIM 1024
#define OUT_DIM 904
#define NC 320                  /* compact cols: 4 cmd + 300 logmix + 16 pad */
#define M_DIM (S_DIM * B_DIM)   /* 104448 */
#define NARG (M_DIM * 6)
#define NEG_BIG (-1.0e30f)
#define MARGIN 2.5e-3f

__device__ float g_fc2[(size_t)M_DIM * NC];     /* 133.7 MB */
__device__ float gWc[NC * H_DIM];
__device__ float g_bc[NC];
__device__ int g_karr[NARG];
__device__ int g_ccnt, g_mcnt;
__device__ int g_clist[M_DIM];
__device__ int g_mlist[NARG];

// ---------------- Threefry / sampling helpers (proven exact R4/R8) ----------------
__device__ __forceinline__ uint2 tf2x32(uint32_t k0, uint32_t k1, uint32_t c0, uint32_t c1) {
    uint32_t ks2 = k0 ^ k1 ^ 0x1BD11BDAu;
    uint32_t x0 = c0 + k0, x1 = c1 + k1;
    uint32_t ks[3] = {k0, k1, ks2};
    const int RA[4] = {13, 15, 26, 6};
    const int RB[4] = {17, 29, 16, 24};
#pragma unroll
    for (int blk = 0; blk < 5; blk++) {
        const int* rr = (blk & 1) ? RB : RA;
#pragma unroll
        for (int i = 0; i < 4; i++) { x0 += x1; x1 = __funnelshift_l(x1, x1, rr[i]); x1 ^= x0; }
        x0 += ks[(blk + 1) % 3];
        x1 += ks[(blk + 2) % 3] + (uint32_t)(blk + 1);
    }
    return make_uint2(x0, x1);
}
__device__ __forceinline__ uint32_t rand32(uint32_t k0, uint32_t k1, uint32_t idx) {
    uint2 r = tf2x32(k0, k1, 0u, idx);
    return r.x ^ r.y;
}
__device__ __forceinline__ float gumbel_u32(uint32_t bits) {
    float f = __uint_as_float((bits >> 9) | 0x3f800000u) - 1.0f;
    float u = fmaxf(f, 1.17549435e-38f);
    return -logf(-logf(u));
}
__device__ __forceinline__ float normal_u32(uint32_t bits) {
    float f = __uint_as_float((bits >> 9) | 0x3f800000u) - 1.0f;
    const float lo = -0.99999994f;
    float u = fmaxf(f * 2.0f + lo, lo);
    return 1.41421356237f * erfinvf(u);
}

__global__ void zero_counters() { g_ccnt = 0; g_mcnt = 0; }

// ---------------- compact W: rows {0..3} + {4+j*150+c : j<6, c<50}, pad zeros ----------------
__global__ void build_Wc(const float* __restrict__ W, const float* __restrict__ bias) {
    int i = blockIdx.x * blockDim.x + threadIdx.x;
    if (i >= NC * H_DIM / 4) return;
    const int row = i >> 8;
    int src;
    if (row < 4) src = row;
    else if (row < 304) { const int t = row - 4; src = 4 + (t / 50) * 150 + (t % 50); }
    else src = -1;
    ((float4*)gWc)[i] = (src >= 0)
        ? ((const float4*)W)[(size_t)src * (H_DIM / 4) + (i & 255)]
        : make_float4(0.f, 0.f, 0.f, 0.f);
    if ((i & 255) == 0) g_bc[row] = (src >= 0) ? bias[src] : 0.0f;
}

// ---------------- GEMM: 256x64 CTA, 8x8 microtile, BK=16, split-row Bs ----------------
#define BM 256
#define BN 64
#define BK 16
#define BS_STRIDE 72
/* Bs col placement: cols 0..31 at word c, cols 32..63 at word c+4 (gap kills
   the 2-way bank conflict between tcol and tcol+4 readers). */
#define BS_COL(c) ((c) < 32 ? (c) : (c) + 4)

__global__ __launch_bounds__(256)
void gemm_kernel(const float* __restrict__ A) {
    __shared__ float As[BK][BM + 4];
    __shared__ float Bs[BK][BS_STRIDE];

    const int tid = threadIdx.x;
    const int tcol = tid & 7;       // 8 col-groups of 8
    const int trow = tid >> 3;      // 32 row-groups of 8
    const int row0 = blockIdx.y * BM;
    const int col0 = blockIdx.x * BN;

    float acc[8][8];
#pragma unroll
    for (int i = 0; i < 8; i++)
#pragma unroll
        for (int j = 0; j < 8; j++) acc[i][j] = 0.0f;

    // global load mapping per BK=16 chunk:
    // A: 256 rows x 4 float4 = 1024 float4 -> 4 per thread (rows lr+t*64)
    // B:  64 rows x 4 float4 =  256 float4 -> 1 per thread
    const int lr = tid >> 2;            // 0..63
    const int lf = (tid & 3) << 2;      // k-offset 0,4,8,12

    const float* Ap = A + (size_t)(row0 + lr) * H_DIM + lf;
    const float* Wp = gWc + (size_t)(col0 + lr) * H_DIM + lf;

    float4 pa[4], pb;
#pragma unroll
    for (int t = 0; t < 4; t++) pa[t] = *(const float4*)(Ap + (size_t)t * 64 * H_DIM);
    pb = *(const float4*)Wp;

    const int bsw = BS_COL(lr);         // write col for Bs (scalar stores)

    for (int k0 = 0; k0 < H_DIM; k0 += BK) {
#pragma unroll
        for (int t = 0; t < 4; t++) {
            const int r = lr + t * 64;
            As[lf + 0][r] = pa[t].x; As[lf + 1][r] = pa[t].y;
            As[lf + 2][r] = pa[t].z; As[lf + 3][r] = pa[t].w;
        }
        Bs[lf + 0][bsw] = pb.x; Bs[lf + 1][bsw] = pb.y;
        Bs[lf + 2][bsw] = pb.z; Bs[lf + 3][bsw] = pb.w;
        __syncthreads();

        const int kn = k0 + BK;
        if (kn < H_DIM) {
#pragma unroll
            for (int t = 0; t < 4; t++)
                pa[t] = *(const float4*)(Ap + (size_t)t * 64 * H_DIM + kn);
            pb = *(const float4*)(Wp + kn);
        }

#pragma unroll
        for (int k = 0; k < BK; k++) {
            float4 a0 = *(const float4*)(&As[k][trow * 8]);
            float4 a1 = *(const float4*)(&As[k][trow * 8 + 4]);
            float4 b0 = *(const float4*)(&Bs[k][BS_COL(tcol * 8)]);
            float4 b1 = *(const float4*)(&Bs[k][BS_COL(tcol * 8) + 4]);
            float av[8] = {a0.x, a0.y, a0.z, a0.w, a1.x, a1.y, a1.z, a1.w};
            float bv[8] = {b0.x, b0.y, b0.z, b0.w, b1.x, b1.y, b1.z, b1.w};
#pragma unroll
            for (int i = 0; i < 8; i++)
#pragma unroll
                for (int j = 0; j < 8; j++)
                    acc[i][j] = fmaf(av[i], bv[j], acc[i][j]);
        }
        __syncthreads();
    }

    const int c = col0 + tcol * 8;
    const float4 bb0 = *(const float4*)(g_bc + c);
    const float4 bb1 = *(const float4*)(g_bc + c + 4);
#pragma unroll
    for (int i = 0; i < 8; i++) {
        const int r = row0 + trow * 8 + i;
        float4 o0, o1;
        o0.x = acc[i][0] + bb0.x; o0.y = acc[i][1] + bb0.y;
        o0.z = acc[i][2] + bb0.z; o0.w = acc[i][3] + bb0.w;
        o1.x = acc[i][4] + bb1.x; o1.y = acc[i][5] + bb1.y;
        o1.z = acc[i][6] + bb1.z; o1.w = acc[i][7] + bb1.w;
        *(float4*)(g_fc2 + (size_t)r * NC + c) = o0;
        *(float4*)(g_fc2 + (size_t)r * NC + c + 4) = o1;
    }
}

// ---------------- command: fast path or push to worklist ----------------
__global__ void command_kernel(float* __restrict__ out) {
    const int row = blockIdx.x * blockDim.x + threadIdx.x;
    if (row >= M_DIM) return;
    const float4 x4 = *(const float4*)(g_fc2 + (size_t)row * NC);
    float x[4] = {x4.x, x4.y, x4.z, x4.w};

    int best = 0; float m = x[0];
#pragma unroll
    for (int c = 1; c < 4; c++) if (x[c] > m) { m = x[c]; best = c; }
    int nnear = 0;
#pragma unroll
    for (int c = 0; c < 4; c++) nnear += (x[c] > m - MARGIN) ? 1 : 0;

    if (nnear > 1) {
        int slot = atomicAdd(&g_ccnt, 1);
        g_clist[slot] = row;
        return;
    }
    float2* o = (float2*)(out + (size_t)row * 10);
    o[0] = make_float2(best == 0 ? 1.f : 0.f, best == 1 ? 1.f : 0.f);
    o[1] = make_float2(best == 2 ? 1.f : 0.f, best == 3 ? 1.f : 0.f);
}

// ---------------- mixture: record winning k (or -1 + worklist) ----------------
__global__ void mixture_kernel() {
    const int gwarp = (blockIdx.x * blockDim.x + threadIdx.x) >> 5;
    const int lane = threadIdx.x & 31;
    if (gwarp >= NARG) return;

    const int sbr = gwarp / 6;
    const int j = gwarp - sbr * 6;
    const float* base = g_fc2 + (size_t)sbr * NC + 4 + j * 50;

    const float x0 = base[lane];
    const float x1 = (lane < 18) ? base[32 + lane] : NEG_BIG;

    float m = fmaxf(x0, x1);
#pragma unroll
    for (int o = 16; o; o >>= 1) m = fmaxf(m, __shfl_xor_sync(0xffffffffu, m, o));

    const float th = m - MARGIN;
    const unsigned f0 = __ballot_sync(0xffffffffu, x0 > th);
    const unsigned f1 = __ballot_sync(0xffffffffu, x1 > th);

    if (lane == 0) {
        if (__popc(f0) + __popc(f1) != 1) {
            g_karr[gwarp] = -1;
            int slot = atomicAdd(&g_mcnt, 1);
            g_mlist[slot] = gwarp;
        } else {
            g_karr[gwarp] = f0 ? (__ffs(f0) - 1) : (31 + __ffs(f1));
        }
    }
}

// ---------------- gather: per row, chosen mean/logstd dots + write args ----------------
__global__ __launch_bounds__(384)
void gather_kernel(const float* __restrict__ A, const float* __restrict__ W,
                   const float* __restrict__ bias, float* __restrict__ out,
                   uint32_t kg0, uint32_t kg1) {
    __shared__ float sa[H_DIM];
    __shared__ float sval[12];
    const int sbr = blockIdx.x;
    const int tid = threadIdx.x;
    const int warp = tid >> 5, lane = tid & 31;

    {
        const float4* src = (const float4*)(A + (size_t)sbr * H_DIM);
        if (tid < 256) ((float4*)sa)[tid] = src[tid];
    }
    __syncthreads();

    const int j = warp >> 1, which = warp & 1;
    const int k = g_karr[sbr * 6 + j];
    if (k >= 0) {
        const int col = 4 + j * 150 + 50 + which * 50 + k;
        const float4* w4 = (const float4*)(W + (size_t)col * H_DIM);
        const float4* s4 = (const float4*)sa;
        float acc = 0.0f;
#pragma unroll
        for (int t = 0; t < 8; t++) {
            const float4 wv = w4[t * 32 + lane];
            const float4 av = s4[t * 32 + lane];
            acc = fmaf(av.x, wv.x, acc);
            acc = fmaf(av.y, wv.y, acc);
            acc = fmaf(av.z, wv.z, acc);
            acc = fmaf(av.w, wv.w, acc);
        }
#pragma unroll
        for (int o = 16; o; o >>= 1) acc += __shfl_xor_sync(0xffffffffu, acc, o);
        if (lane == 0) sval[warp] = acc + bias[col];
    }
    __syncthreads();

    if (tid < 6) {
        const int kk = g_karr[sbr * 6 + tid];
        if (kk >= 0) {
            const float mean = sval[tid * 2];
            const float lstd = sval[tid * 2 + 1];
            const float n = normal_u32(rand32(kg0, kg1, (uint32_t)(sbr * 6 + tid)));
            out[(size_t)sbr * 10 + 4 + tid] = mean + expf(lstd) * (n * 0.01f);
        }
    }
}

// ---------------- cmd fixup: exact sequential recompute (proven R8) ----------------
__global__ void cmd_fixup(const float* __restrict__ A, const float* __restrict__ W,
                          const float* __restrict__ bias, float* __restrict__ out,
                          uint32_t kc0, uint32_t kc1) {
    const int nwarp = (gridDim.x * blockDim.x) >> 5;
    const int lane = threadIdx.x & 31;
    for (int e = (blockIdx.x * blockDim.x + threadIdx.x) >> 5; e < g_ccnt; e += nwarp) {
        const int row = g_clist[e];
        float sc = NEG_BIG;
        if (lane < 4) {
            const float* a = A + (size_t)row * H_DIM;
            const float* w = W + (size_t)lane * H_DIM;
            float acc = 0.0f;
            for (int k = 0; k < H_DIM; k++) acc = fmaf(a[k], w[k], acc);
            const float x = acc + bias[lane];
            sc = gumbel_u32(rand32(kc0, kc1, (uint32_t)(row * 4 + lane))) +
                 __fdiv_rn(x, 1e-4f);
        }
        int bi = lane;
#pragma unroll
        for (int o = 1; o < 4; o <<= 1) {
            float os = __shfl_xor_sync(0xffffffffu, sc, o);
            int oi = __shfl_xor_sync(0xffffffffu, bi, o);
            if (os > sc || (os == sc && oi < bi)) { sc = os; bi = oi; }
        }
        if (lane == 0) {
            float2* o2 = (float2*)(out + (size_t)row * 10);
            o2[0] = make_float2(bi == 0 ? 1.f : 0.f, bi == 1 ? 1.f : 0.f);
            o2[1] = make_float2(bi == 2 ? 1.f : 0.f, bi == 3 ? 1.f : 0.f);
        }
    }
}

// ---------------- mix fixup: exact sequential recompute incl. mean/logstd ----------------
__global__ __launch_bounds__(64)
void mix_fixup(const float* __restrict__ A, const float* __restrict__ W,
               const float* __restrict__ bias, float* __restrict__ out,
               uint32_t km0, uint32_t km1, uint32_t kg0, uint32_t kg1) {
    __shared__ float sa[H_DIM];
    __shared__ float sx[50];
    for (int e = blockIdx.x; e < g_mcnt; e += gridDim.x) {
        const int gw = g_mlist[e];
        const int sbr = gw / 6;
        const int j = gw - sbr * 6;
        __syncthreads();
        {
            const float4* src = (const float4*)(A + (size_t)sbr * H_DIM);
            float4* dst = (float4*)sa;
            for (int i = threadIdx.x; i < H_DIM / 4; i += 64) dst[i] = src[i];
        }
        __syncthreads();
        const int c = threadIdx.x;
        if (c < 50) {
            const int col = 4 + j * 150 + c;
            const float* w = W + (size_t)col * H_DIM;
            float acc = 0.0f;
            for (int k = 0; k < H_DIM; k++) acc = fmaf(sa[k], w[k], acc);
            sx[c] = acc + bias[col];
        }
        __syncthreads();
        if (threadIdx.x == 0) {
            float m = sx[0];
            for (int i = 1; i < 50; i++) m = fmaxf(m, sx[i]);
            float s = 0.0f;
            for (int i = 0; i < 50; i++) s += expf(sx[i] - m);
            const float lse = logf(s) + m;
            float bsc = NEG_BIG; int bk = 0;
            const uint32_t eb = (uint32_t)gw * 50u;
            for (int i = 0; i < 50; i++) {
                const float g = gumbel_u32(rand32(km0, km1, eb + (uint32_t)i));
                const float sc = g + __fdiv_rn(sx[i] - lse, 1e-4f);
                if (sc > bsc) { bsc = sc; bk = i; }
            }
            const int cm = 4 + j * 150 + 50 + bk;
            const int cl = cm + 50;
            const float* wm = W + (size_t)cm * H_DIM;
            const float* wl = W + (size_t)cl * H_DIM;
            float am = 0.0f, al = 0.0f;
            for (int k = 0; k < H_DIM; k++) {
                am = fmaf(sa[k], wm[k], am);
                al = fmaf(sa[k], wl[k], al);
            }
            const float mean = am + bias[cm];
            const float lstd = al + bias[cl];
            const float n = normal_u32(rand32(kg0, kg1, (uint32_t)gw));
            out[(size_t)sbr * 10 + 4 + j] = mean + expf(lstd) * (n * 0.01f);
        }
    }
}

// ---------------- host threefry ----------------
static inline uint32_t h_rotl(uint32_t v, int r) { return (v << r) | (v >> (32 - r)); }
static void h_tf(uint32_t k0, uint32_t k1, uint32_t c0, uint32_t c1,
                 uint32_t* o0, uint32_t* o1) {
    uint32_t ks2 = k0 ^ k1 ^ 0x1BD11BDAu;
    uint32_t x0 = c0 + k0, x1 = c1 + k1;
    uint32_t ks[3] = {k0, k1, ks2};
    const int RA[4] = {13, 15, 26, 6};
    const int RB[4] = {17, 29, 16, 24};
    for (int blk = 0; blk < 5; blk++) {
        const int* rr = (blk & 1) ? RB : RA;
        for (int i = 0; i < 4; i++) { x0 += x1; x1 = h_rotl(x1, rr[i]); x1 ^= x0; }
        x0 += ks[(blk + 1) % 3];
        x1 += ks[(blk + 2) % 3] + (uint32_t)(blk + 1);
    }
    *o0 = x0; *o1 = x1;
}

extern "C" void kernel_launch(void* const* d_in, const int* in_sizes, int n_in,
                              void* d_out, int out_size) {
    const float* A = (const float*)d_in[0];
    const float* W = (const float*)d_in[1];
    const float* b = (const float*)d_in[2];
    float* out = (float*)d_out;

    uint32_t kc0, kc1, km0, km1, kg0, kg1;
    h_tf(0u, 42u, 0u, 0u, &kc0, &kc1);
    h_tf(0u, 42u, 0u, 1u, &km0, &km1);
    h_tf(0u, 42u, 0u, 2u, &kg0, &kg1);

    zero_counters<<<1, 1>>>();
    build_Wc<<<(NC * H_DIM / 4 + 255) / 256, 256>>>(W, b);
    gemm_kernel<<<dim3(NC / BN, M_DIM / BM), 256>>>(A);
    command_kernel<<<(M_DIM + 255) / 256, 256>>>(out);

    const int mwpb = 8;
    mixture_kernel<<<(NARG + mwpb - 1) / mwpb, mwpb * 32>>>();
    gather_kernel<<<M_DIM, 384>>>(A, W, b, out, kg0, kg1);

    cmd_fixup<<<1024, 256>>>(A, W, b, out, kc0, kc1);
    mix_fixup<<<8192, 64>>>(A, W, b, out, km0, km1, kg0, kg1);
}